// round 15
// baseline (speedup 1.0000x reference)
#include <cuda_runtime.h>

#define SS 512
#define EE 8
#define FF 4
#define FH 8    // F * num_heads
#define NT 128  // threads per block
#define NR 4    // s-rows per thread
#define PGRID 912  // 152 SMs * 6 resident CTAs

// Batch-independent precomputed cross-attention query-side terms:
// score[f,h,s] = x[s,:] . g_A[f*2+h,:] + g_c[f*2+h]
__device__ float g_A[FH][EE];
__device__ float g_c[FH];

// 32-thread parallel version of the batch-independent precompute.
__global__ void precompute_kernel(const float* __restrict__ Q,
                                  const float* __restrict__ sa_w_in,
                                  const float* __restrict__ sa_b_in,
                                  const float* __restrict__ sa_w_out,
                                  const float* __restrict__ sa_b_out,
                                  const float* __restrict__ ca_w_in,
                                  const float* __restrict__ ca_b_in) {
    __shared__ float qh[32], kh[32], vh[32], ctx[32], qu[32], qc[32];
    const int lane = threadIdx.x;           // 32 threads
    const int f = lane >> 3, ep = lane & 7;  // (f, ep) for 4x8 outputs

    // in-proj of the factor queries
    {
        float aq = sa_b_in[ep], ak = sa_b_in[8 + ep], av = sa_b_in[16 + ep];
        for (int e = 0; e < EE; e++) {
            float qe = Q[f * EE + e];
            aq += qe * sa_w_in[ep * EE + e];
            ak += qe * sa_w_in[(8 + ep) * EE + e];
            av += qe * sa_w_in[(16 + ep) * EE + e];
        }
        qh[lane] = aq; kh[lane] = ak; vh[lane] = av;
    }
    __syncwarp();

    // self-attention over the 4 factors (per-lane redundant softmax, cheap)
    {
        int h = ep >> 2, d = ep & 3;
        float sc[FF], mx = -1e30f;
        for (int m = 0; m < FF; m++) {
            float s = 0.f;
            for (int dd = 0; dd < 4; dd++)
                s += qh[f * 8 + h * 4 + dd] * kh[m * 8 + h * 4 + dd];
            s *= 0.5f;  // 1/sqrt(Dh=4)
            sc[m] = s; mx = fmaxf(mx, s);
        }
        float sum = 0.f;
        for (int m = 0; m < FF; m++) { sc[m] = expf(sc[m] - mx); sum += sc[m]; }
        float a = 0.f;
        for (int m = 0; m < FF; m++) a += sc[m] * vh[m * 8 + h * 4 + d];
        ctx[lane] = a / sum;
    }
    __syncwarp();

    // out-proj
    {
        float a = sa_b_out[ep];
        for (int e = 0; e < EE; e++) a += ctx[f * 8 + e] * sa_w_out[ep * EE + e];
        qu[lane] = a;
    }
    __syncwarp();

    // cross-attention q-projection, pre-scaled by 1/sqrt(4)
    {
        float a = ca_b_in[ep];
        for (int e = 0; e < EE; e++) a += qu[f * 8 + e] * ca_w_in[ep * EE + e];
        qc[lane] = a * 0.5f;
    }
    __syncwarp();

    // fold q into k projection
    if (lane < 8) {
        int ff = lane >> 1, h = lane & 1;
        float c = 0.f;
        for (int d = 0; d < 4; d++) c += qc[ff * 8 + h * 4 + d] * ca_b_in[8 + h * 4 + d];
        g_c[lane] = c;
    }
#pragma unroll
    for (int rep = 0; rep < 2; rep++) {
        int e2 = lane + 32 * rep;           // 0..63 over [fh][e]
        int fh = e2 >> 3, e = e2 & 7;
        int ff = fh >> 1, h = fh & 1;
        float a = 0.f;
        for (int d = 0; d < 4; d++)
            a += qc[ff * 8 + h * 4 + d] * ca_w_in[(8 + h * 4 + d) * EE + e];
        g_A[fh][e] = a;
    }
}

// Split-payload warp reduction of 9 values across 32 lanes: 12 SHFL total.
// After the call, the lane's v[0] holds the full-warp sum of ONE entry
// (entry index = 'start' computed by the caller, valid on even lanes with nreal>0).
__device__ __forceinline__ float warp_reduce9(float v[9]) {
    const int lane = threadIdx.x & 31;
    bool hi = (lane & 16);
#pragma unroll
    for (int i = 0; i < 5; i++) {
        float up = (i + 5 < 9) ? v[i + 5] : 0.f;
        float send = hi ? v[i] : up;
        float t = __shfl_xor_sync(~0u, send, 16);
        v[i] = (hi ? up : v[i]) + t;
    }
    hi = (lane & 8);
#pragma unroll
    for (int i = 0; i < 3; i++) {
        float up = (i + 3 < 5) ? v[i + 3] : 0.f;
        float send = hi ? v[i] : up;
        float t = __shfl_xor_sync(~0u, send, 8);
        v[i] = (hi ? up : v[i]) + t;
    }
    hi = (lane & 4);
#pragma unroll
    for (int i = 0; i < 2; i++) {
        float up = (i + 2 < 3) ? v[i + 2] : 0.f;
        float send = hi ? v[i] : up;
        float t = __shfl_xor_sync(~0u, send, 4);
        v[i] = (hi ? up : v[i]) + t;
    }
    hi = (lane & 2);
    {
        float send = hi ? v[0] : v[1];
        float t = __shfl_xor_sync(~0u, send, 2);
        v[0] = (hi ? v[1] : v[0]) + t;
    }
    v[0] += __shfl_xor_sync(~0u, v[0], 1);
    return v[0];
}

__global__ __launch_bounds__(NT, 6) void afs_main_kernel(
    const float* __restrict__ x,
    const float* __restrict__ r_b2,
    float* __restrict__ outv, float* __restrict__ sim,
    const float* __restrict__ ca_w_in, const float* __restrict__ ca_b_in,
    const float* __restrict__ ca_w_out, const float* __restrict__ ca_b_out,
    const float* __restrict__ r_w1, const float* __restrict__ r_b1,
    const float* __restrict__ r_w2, int B)
{
    __shared__ float pacc[4][96];       // [src warp][fh*12 + k], k<9 used
    __shared__ float red[80];           // combined entries (72 / 36)
    __shared__ float sA[8][8];
    __shared__ float scc[8];
    __shared__ float sqc[32];
    __shared__ float swv[8][8];
    __shared__ float sbv[8];
    __shared__ float swo[8][8];
    __shared__ float sbo[8];
    __shared__ float sctx[32];
    __shared__ float sfin[32];
    __shared__ float srw1[16 * 33];     // padded stride 33
    __shared__ float srb1[16];
    __shared__ float srw2[16];
    __shared__ float sb2;

    const int tid = threadIdx.x;
    const int w = tid >> 5, lane = tid & 31;

    // ---- owned-entry bookkeeping for warp_reduce9 (loop-invariant) ----
    int start = 0, nreal = 9;
    if (lane & 16) { start += 5; nreal -= 5; } else nreal = 5;
    if (lane & 8)  { start += 3; nreal -= 3; } else nreal = (nreal < 3 ? nreal : 3);
    if (lane & 4)  { start += 2; nreal -= 2; } else nreal = (nreal < 2 ? nreal : 2);
    if (lane & 2)  { start += 1; nreal -= 1; } else nreal = (nreal < 1 ? nreal : 1);
    const bool wvalid = (nreal > 0) && !(lane & 1);

    // ---- weights to smem ONCE per persistent CTA ----
#pragma unroll
    for (int i = tid; i < 256; i += NT) {
        if (i < 64)       ((float*)sA)[i]        = ((const float*)g_A)[i];
        else if (i < 72)  scc[i - 64]            = g_c[i - 64];
        else if (i < 136) ((float*)swv)[i - 72]  = ca_w_in[16 * EE + (i - 72)];
        else if (i < 144) sbv[i - 136]           = ca_b_in[16 + (i - 136)];
        else if (i < 208) ((float*)swo)[i - 144] = ca_w_out[i - 144];
        else if (i < 216) sbo[i - 208]           = ca_b_out[i - 208];
        else if (i < 232) srb1[i - 216]          = r_b1[i - 216];
        else if (i < 248) srw2[i - 232]          = r_w2[i - 232];
        else if (i == 248) sb2                   = r_b2[0];
    }
#pragma unroll
    for (int i = tid; i < 512; i += NT) srw1[(i >> 5) * 33 + (i & 31)] = r_w1[i];
    __syncthreads();

    // ---- persistent loop over batches ----
    for (int b = blockIdx.x; b < B; b += gridDim.x) {

        // load x rows s = tid + 128*r, r=0..3, into registers
        const float4* __restrict__ xin = (const float4*)(x + (size_t)b * (SS * EE));
        float xr[NR][EE];
#pragma unroll
        for (int r = 0; r < NR; r++) {
            float4 a0 = xin[2 * (tid + NT * r)];
            float4 a1 = xin[2 * (tid + NT * r) + 1];
            xr[r][0] = a0.x; xr[r][1] = a0.y; xr[r][2] = a0.z; xr[r][3] = a0.w;
            xr[r][4] = a1.x; xr[r][5] = a1.y; xr[r][6] = a1.z; xr[r][7] = a1.w;
        }

        // prefetch next batch's x tile into L2 (one 128B line per thread = 16 KB)
        {
            int bn = b + gridDim.x;
            if (bn < B) {
                const char* xb = (const char*)(x + (size_t)bn * (SS * EE));
                asm volatile("prefetch.global.L2 [%0];" :: "l"(xb + tid * 128));
            }
        }

        // ---- P1+P3: scores -> exp (no max; bounded) -> partials -> reduce ----
#pragma unroll
        for (int fh = 0; fh < 8; fh++) {
            float wgt[NR];
#pragma unroll
            for (int r = 0; r < NR; r++) {
                float a = scc[fh];
#pragma unroll
                for (int e = 0; e < 8; e++) a += sA[fh][e] * xr[r][e];
                wgt[r] = __expf(a);
            }
            float q[9];
#pragma unroll
            for (int e = 0; e < 8; e++) {
                float a = wgt[0] * xr[0][e];
#pragma unroll
                for (int r = 1; r < NR; r++) a = fmaf(wgt[r], xr[r][e], a);
                q[e] = a;
            }
            q[8] = (wgt[0] + wgt[1]) + (wgt[2] + wgt[3]);
            float rr = warp_reduce9(q);
            if (wvalid) pacc[w][fh * 12 + start] = rr;
        }
        __syncthreads();

        // ---- combine 4 warp-partials: thread t<72 handles one entry ----
        if (tid < 72) {
            int fh = tid / 9, k = tid - fh * 9;
            red[tid] = (pacc[0][fh * 12 + k] + pacc[1][fh * 12 + k])
                     + (pacc[2][fh * 12 + k] + pacc[3][fh * 12 + k]);
        }
        __syncthreads();

        // ---- P5: warp 0: ctx -> Q_cross ----
        if (w == 0) {
            {
                int f = lane >> 3, r = lane & 7;
                int fh = f * 2 + (r >> 2);
                float inv = 1.0f / red[fh * 9 + 8];
                float a = 0.f;
#pragma unroll
                for (int e = 0; e < 8; e++) a += red[fh * 9 + e] * swv[r][e];
                sctx[lane] = a * inv + sbv[r];
            }
            __syncwarp();
            {
                int f = lane >> 3, ep = lane & 7;
                float a = sbo[ep];
#pragma unroll
                for (int e = 0; e < 8; e++) a += sctx[f * 8 + e] * swo[ep][e];
                sqc[f * 8 + ep] = a;
            }
        }
        __syncthreads();

        // ---- P6+P7: similarity -> gmem; exp -> partials -> reduce ----
        float* __restrict__ simo = sim + (size_t)b * (FF * SS);
#pragma unroll
        for (int f = 0; f < 4; f++) {
            float wgt[NR];
#pragma unroll
            for (int r = 0; r < NR; r++) {
                float a = 0.f;
#pragma unroll
                for (int e = 0; e < 8; e++) a += sqc[f * 8 + e] * xr[r][e];
                simo[f * SS + tid + NT * r] = a;
                wgt[r] = __expf(a);
            }
            float q[9];
#pragma unroll
            for (int e = 0; e < 8; e++) {
                float a = wgt[0] * xr[0][e];
#pragma unroll
                for (int r = 1; r < NR; r++) a = fmaf(wgt[r], xr[r][e], a);
                q[e] = a;
            }
            q[8] = (wgt[0] + wgt[1]) + (wgt[2] + wgt[3]);
            float rr = warp_reduce9(q);
            if (wvalid) pacc[w][f * 12 + start] = rr;
        }
        __syncthreads();

        // ---- combine: thread t<36 handles one entry ----
        if (tid < 36) {
            int f = tid / 9, k = tid - f * 9;
            red[tid] = (pacc[0][f * 12 + k] + pacc[1][f * 12 + k])
                     + (pacc[2][f * 12 + k] + pacc[3][f * 12 + k]);
        }
        __syncthreads();

        // ---- P8: warp 0: final factors + MLP head ----
        if (w == 0) {
            {
                int f = lane >> 3, e = lane & 7;
                sfin[lane] = red[f * 9 + e] / red[f * 9 + 8];
            }
            __syncwarp();
            float v = 0.f;
            if (lane < 16) {
                float a = srb1[lane];
#pragma unroll
                for (int j = 0; j < 32; j++) a += sfin[j] * srw1[lane * 33 + j];
                v = fmaxf(a, 0.f) * srw2[lane];
            }
#pragma unroll
            for (int o = 16; o > 0; o >>= 1) v += __shfl_xor_sync(~0u, v, o);
            if (lane == 0) outv[b] = v + sb2;
        }
        // no barrier needed here: next iteration's first smem write (pacc)
        // happens only after the combine-stage __syncthreads, and warp 0's
        // red/srw1 reads complete before it arrives there.
    }
}

extern "C" void kernel_launch(void* const* d_in, const int* in_sizes, int n_in,
                              void* d_out, int out_size) {
    const float* x        = (const float*)d_in[0];
    const float* Q        = (const float*)d_in[1];
    const float* sa_w_in  = (const float*)d_in[2];
    const float* sa_b_in  = (const float*)d_in[3];
    const float* sa_w_out = (const float*)d_in[4];
    const float* sa_b_out = (const float*)d_in[5];
    const float* ca_w_in  = (const float*)d_in[6];
    const float* ca_b_in  = (const float*)d_in[7];
    const float* ca_w_out = (const float*)d_in[8];
    const float* ca_b_out = (const float*)d_in[9];
    const float* r_w1     = (const float*)d_in[10];
    const float* r_b1     = (const float*)d_in[11];
    const float* r_w2     = (const float*)d_in[12];
    const float* r_b2     = (const float*)d_in[13];

    int B = in_sizes[0] / (SS * EE);
    float* outv = (float*)d_out;          // [B] first return value
    float* sim  = outv + B;               // [B, F, S] second return value

    int grid = B < PGRID ? B : PGRID;

    precompute_kernel<<<1, 32>>>(Q, sa_w_in, sa_b_in, sa_w_out, sa_b_out, ca_w_in, ca_b_in);
    afs_main_kernel<<<grid, NT>>>(x, r_b2, outv, sim,
                                  ca_w_in, ca_b_in, ca_w_out, ca_b_out,
                                  r_w1, r_b1, r_w2, B);
}